// round 17
// baseline (speedup 1.0000x reference)
#include <cuda_runtime.h>
#include <math_constants.h>
#include <cstdint>

#define NROWS 100000
#define DIM   1024
#define RNUM  64

#define SEG        1024
#define NSEG_CKPT  97          // boundaries at rows 1024..99328

// colsum pipeline: 32 blocks x 32 cols, 256-row tiles, 4-stage cp.async ring,
// fed from the TRANSPOSED copy. CS_PAD=257 (odd) -> consumer LDS conflict-free;
// 4-byte cp.async removes the 16B-alignment constraint that forced even pads.
#define CS_BLOCKS 32
#define CS_COLS   32
#define CS_T      256
#define CS_PAD    257
#define CS_S      4
#define CS_SMEM   (CS_S * CS_COLS * CS_PAD * 4)   // 131,584 B

// dots (measured 81us @ 64% DRAM): 256 rows/block, 32-col smem chunks
#define DR   256
#define DCH  32
#define DBLK ((NROWS + DR - 1) / DR)    // 391

// -------- scratch (no allocations allowed) --------
__device__ float g_xT[DIM * NROWS];       // transposed x: column-major streams (400 MB)
__device__ float g_ckpt[NSEG_CKPT][DIM];  // chain state after rows [0,(s+1)*SEG)
__device__ float g_m[DIM];
__device__ float g_taken[NROWS];
__device__ int   g_takenList[RNUM];       // sorted ascending, distinct taken rows
__device__ int   g_nTaken;
__device__ int   g_remaining;
__device__ int   g_restartSeg;            // first segment whose chain changed
__device__ float g_bScore[DBLK];
__device__ int   g_bIdx[DBLK];
__device__ int   g_sel[RNUM];
__device__ int   g_selSorted[RNUM];

// -------- init (graph replays must fully reset state) --------
__global__ void init_kernel() {
    int i = blockIdx.x * blockDim.x + threadIdx.x;
    if (i < NROWS) g_taken[i] = 0.0f;
    if (i == 0) { g_remaining = NROWS; g_nTaken = 0; g_restartSeg = 0; }
}

// -------- one-time transpose: g_xT[c*NROWS + r] = x[r*DIM + c] --------------
__global__ void transpose_kernel(const float* __restrict__ x) {
    __shared__ float tile[32][33];
    int cBase = blockIdx.x * 32;
    int rBase = blockIdx.y * 32;
    int tx = threadIdx.x, ty = threadIdx.y;
#pragma unroll
    for (int i = ty; i < 32; i += 8)
        tile[i][tx] = x[(size_t)(rBase + i) * DIM + cBase + tx];
    __syncthreads();
#pragma unroll
    for (int i = ty; i < 32; i += 8)
        g_xT[(size_t)(cBase + i) * NROWS + rBase + tx] = tile[tx][i];
}

__device__ __forceinline__ void cp_async4(uint32_t saddr, const float* gptr) {
    asm volatile("cp.async.ca.shared.global [%0], [%1], 4;" :: "r"(saddr), "l"(gptr));
}

// producers (threads 32..255): one 256-row x 32-col tile = 8192 x 4B ops.
// op o: c = o>>8 (column), j = o&255 (row) -> consecutive lanes read
// consecutive rows of one g_xT column (coalesced) and write consecutive
// smem words (conflict-free).
__device__ __forceinline__ void cs_issue(uint32_t bufAddr,
                                         int rStart, int ti, int colBase, int t) {
    int r0 = rStart + ti * CS_T;
    int st = ti & (CS_S - 1);
    uint32_t stBase = bufAddr + (uint32_t)(st * CS_COLS * CS_PAD * 4);
    int p = t - 32;                       // 0..223
#pragma unroll 4
    for (int o = p; o < CS_T * CS_COLS; o += 224) {
        int c = o >> 8;
        int j = o & 255;
        int gr = r0 + j;
        if (gr < NROWS)
            cp_async4(stBase + (uint32_t)((c * CS_PAD + j) * 4),
                      g_xT + (size_t)(colBase + c) * NROWS + gr);
    }
}

// -------- colsum: bit-exact sequential fadd chain per column (validated R8-R16),
// warp-specialized; smem tiles [col][CS_PAD=257] -> conflict-free consumer LDS.
__global__ void __launch_bounds__(256) colsum_kernel() {
    extern __shared__ float buf[];               // [CS_S][CS_COLS][CS_PAD]
    __shared__ int sList[RNUM];
    __shared__ int sMeta[3];

    int t = threadIdx.x;
    if (t == 0) { sMeta[0] = g_nTaken; sMeta[1] = g_restartSeg; sMeta[2] = g_remaining; }
    __syncthreads();
    int sN = sMeta[0], sSeg = sMeta[1], sRem = sMeta[2];
    if (t < RNUM && t < sN) sList[t] = g_takenList[t];
    __syncthreads();

    int colBase = blockIdx.x * CS_COLS;
    int rStart = sSeg << 10;
    int ntiles = (NROWS - rStart + CS_T - 1) / CS_T;

    uint32_t bufAddr = (uint32_t)__cvta_generic_to_shared(buf);
    bool producer = (t >= 32);

    // prologue: tiles 0..2 in flight
#pragma unroll
    for (int ti = 0; ti < CS_S - 1; ti++) {
        if (producer && ti < ntiles) cs_issue(bufAddr, rStart, ti, colBase, t);
        asm volatile("cp.async.commit_group;");
    }

    // consumer chain state (lanes 0..31 of warp 0); lane t owns column colBase+t
    float acc = 0.0f;
    int p = 0, nxt = 0x7fffffff;
    if (t < CS_COLS) {
        if (sSeg > 0) acc = g_ckpt[sSeg - 1][colBase + t];
        while (p < sN && sList[p] < rStart) p++;
        nxt = (p < sN) ? sList[p] : 0x7fffffff;
    }

    for (int i = 0; i < ntiles; i++) {
        asm volatile("cp.async.wait_group 2;");  // tile i complete
        __syncthreads();
        if (producer && (i + CS_S - 1) < ntiles)
            cs_issue(bufAddr, rStart, i + CS_S - 1, colBase, t);
        asm volatile("cp.async.commit_group;");

        if (t < CS_COLS) {
            const float* s = buf + (i & (CS_S - 1)) * CS_COLS * CS_PAD + t * CS_PAD;
            int r0 = rStart + i * CS_T;
            int nr = min(CS_T, NROWS - r0);
            bool slow = (nr < CS_T) || (nxt < r0 + nr);
            if (!slow) {
                // pure chain, software-pipelined 16-row register batches
                float v0[16], v1[16];
#define LOADB(arr, b) { _Pragma("unroll") \
    for (int j = 0; j < 16; j++) arr[j] = s[((b) << 4) + j]; }
#define CHAINB(arr) { _Pragma("unroll") \
    for (int j = 0; j < 16; j++) acc = __fadd_rn(acc, arr[j]); }
                LOADB(v0, 0)
#pragma unroll
                for (int b = 0; b < CS_T / 16; b++) {
                    if (b & 1) { if (b + 1 < CS_T / 16) LOADB(v0, b + 1) CHAINB(v1) }
                    else       { if (b + 1 < CS_T / 16) LOADB(v1, b + 1) CHAINB(v0) }
                }
                if (((r0 + CS_T) & (SEG - 1)) == 0)
                    g_ckpt[((r0 + CS_T) >> 10) - 1][colBase + t] = acc;
            } else {
                for (int j = 0; j < nr; j++) {
                    int r = r0 + j;
                    float v = s[j];
                    if (r == nxt) { p++; nxt = (p < sN) ? sList[p] : 0x7fffffff; }
                    else acc = __fadd_rn(acc, v);
                    if (((r + 1) & (SEG - 1)) == 0)
                        g_ckpt[((r + 1) >> 10) - 1][colBase + t] = acc;
                }
            }
        }
        __syncthreads();
    }
    asm volatile("cp.async.wait_group 0;");
    if (t < CS_COLS)
        g_m[colBase + t] = __fdiv_rn(acc, (float)sRem);
}

// -------- dots + block argmax: Eigen 4-chain FMA order (validated R8-R16),
// measured 81us @ 64% DRAM — unchanged. ----------------------------------
__global__ void __launch_bounds__(DR) dots_argmax_kernel(const float* __restrict__ x) {
    __shared__ float tile[DR][DCH + 1];      // stride 33: conflict-free
    __shared__ float ms[DCH];
    __shared__ float sSc[DR];
    __shared__ int   sIx[DR];

    int t = threadIdx.x;
    int row0 = blockIdx.x * DR;
    int row = row0 + t;
    bool valid = row < NROWS;

    float a0 = 0.0f, a1 = 0.0f, a2 = 0.0f, a3 = 0.0f;

    for (int cb = 0; cb < DIM / DCH; cb++) {
        // load 256 rows x 32 cols as float4 (8 per thread), coalesced
#pragma unroll
        for (int f = 0; f < 8; f++) {
            int idx = t + f * DR;
            int r = idx >> 3;
            int c4 = idx & 7;
            int gr = row0 + r;
            float4 v = make_float4(0.f, 0.f, 0.f, 0.f);
            if (gr < NROWS)
                v = ((const float4*)(x + (size_t)gr * DIM + cb * DCH))[c4];
            tile[r][c4 * 4 + 0] = v.x;
            tile[r][c4 * 4 + 1] = v.y;
            tile[r][c4 * 4 + 2] = v.z;
            tile[r][c4 * 4 + 3] = v.w;
        }
        if (t < DCH) ms[t] = g_m[cb * DCH + t];
        __syncthreads();
        if (valid) {
#pragma unroll
            for (int c = 0; c < DCH; c += 4) {
                a0 = __fmaf_rn(tile[t][c + 0], ms[c + 0], a0);
                a1 = __fmaf_rn(tile[t][c + 1], ms[c + 1], a1);
                a2 = __fmaf_rn(tile[t][c + 2], ms[c + 2], a2);
                a3 = __fmaf_rn(tile[t][c + 3], ms[c + 3], a3);
            }
        }
        __syncthreads();
    }

    float score = -CUDART_INF_F;
    if (valid) {
        float dot = __fadd_rn(__fadd_rn(a0, a1), __fadd_rn(a2, a3));
        score = __fadd_rn(__fdiv_rn(1.0f, dot), g_taken[row]);
    }
    sSc[t] = score;
    sIx[t] = row;
    __syncthreads();
    for (int off = DR / 2; off > 0; off >>= 1) {
        if (t < off) {
            float s = sSc[t + off];
            int  id = sIx[t + off];
            if (s > sSc[t] || (s == sSc[t] && id < sIx[t])) { sSc[t] = s; sIx[t] = id; }
        }
        __syncthreads();
    }
    if (t == 0) { g_bScore[blockIdx.x] = sSc[0]; g_bIdx[blockIdx.x] = sIx[0]; }
}

// -------- finalize: global argmax over 391 blocks; maintain taken state -----
__global__ void finalize_kernel(int k) {
    __shared__ float sSc[256];
    __shared__ int   sIx[256];

    float best = -CUDART_INF_F;
    int   bi = 0x7fffffff;
    for (int i = threadIdx.x; i < DBLK; i += 256) {
        float s = g_bScore[i];
        int  id = g_bIdx[i];
        if (s > best || (s == best && id < bi)) { best = s; bi = id; }
    }
    sSc[threadIdx.x] = best;
    sIx[threadIdx.x] = bi;
    __syncthreads();
    for (int off = 128; off > 0; off >>= 1) {
        if (threadIdx.x < off) {
            float s = sSc[threadIdx.x + off];
            int  id = sIx[threadIdx.x + off];
            if (s > sSc[threadIdx.x] || (s == sSc[threadIdx.x] && id < sIx[threadIdx.x])) {
                sSc[threadIdx.x] = s;
                sIx[threadIdx.x] = id;
            }
        }
        __syncthreads();
    }
    if (threadIdx.x == 0) {
        int w = sIx[0];
        g_sel[k] = w;
        float t = g_taken[w];
        g_taken[w] = __fadd_rn(t, -100000.0f);
        if (t == 0.0f) {
            g_remaining -= 1;
            int n = g_nTaken;
            int pos = n;
            while (pos > 0 && g_takenList[pos - 1] > w) {
                g_takenList[pos] = g_takenList[pos - 1];
                pos--;
            }
            g_takenList[pos] = w;
            g_nTaken = n + 1;
        }
        g_restartSeg = w >> 10;   // chain changes from row w onward
    }
}

// -------- epilogue: rank sort (duplicate-safe), gather rows --------
__global__ void sortsel_kernel() {
    int t = threadIdx.x;            // 64 threads
    int v = g_sel[t];
    int r = 0;
    for (int j = 0; j < RNUM; j++) {
        int u = g_sel[j];
        r += (u < v) || (u == v && j < t);
    }
    g_selSorted[r] = v;
}

__global__ void gather_kernel(const float* __restrict__ x, float* __restrict__ out) {
    int row = g_selSorted[blockIdx.x];
    const float4* src = (const float4*)(x + (size_t)row * DIM);
    float4* dst = (float4*)(out + (size_t)blockIdx.x * DIM);
    dst[threadIdx.x] = src[threadIdx.x];   // 256 threads x float4 = 1024 floats
}

extern "C" void kernel_launch(void* const* d_in, const int* in_sizes, int n_in,
                              void* d_out, int out_size) {
    const float* x = (const float*)d_in[0];
    float* out = (float*)d_out;

    cudaFuncSetAttribute(colsum_kernel,
                         cudaFuncAttributeMaxDynamicSharedMemorySize, CS_SMEM);

    init_kernel<<<(NROWS + 255) / 256, 256>>>();
    transpose_kernel<<<dim3(DIM / 32, NROWS / 32), dim3(32, 8)>>>(x);

    for (int k = 0; k < RNUM; k++) {
        colsum_kernel<<<CS_BLOCKS, 256, CS_SMEM>>>();
        dots_argmax_kernel<<<DBLK, DR>>>(x);
        finalize_kernel<<<1, 256>>>(k);
    }

    sortsel_kernel<<<1, RNUM>>>();
    gather_kernel<<<RNUM, 256>>>(x, out);
}